// round 14
// baseline (speedup 1.0000x reference)
#include <cuda_runtime.h>
#include <cuda_bf16.h>
#include <cstdint>

#define NNODES 100000
#define NEDGES 1600000
#define FIN  128
#define FHID 128
#define FOUT 64

// Scratch (allocation-free rule: __device__ globals)
__device__ float g_dinv[NNODES];
__device__ int   g_deg [NNODES];
__device__ int   g_rowptr[NNODES];
__device__ int   g_cursor[NNODES];
__device__ int   g_adj [NEDGES];
__device__ int   g_blockSums[256];
__device__ float g_GA [NNODES * FHID];   // message buffer A (layers 1, 3)
__device__ float g_GB [NNODES * FHID];   // message buffer B (layer 2)
__device__ float g_ACC[NNODES * FHID];   // aggregated output / next-layer input

// ---------------- helpers ----------------

__device__ __forceinline__ uint32_t smem_u32(const void* p) {
    uint32_t a;
    asm("{ .reg .u64 t; cvta.to.shared.u64 t, %1; cvt.u32.u64 %0, t; }" : "=r"(a) : "l"(p));
    return a;
}

__device__ __forceinline__ void ldm_x4(uint32_t* r, uint32_t addr) {
    asm volatile("ldmatrix.sync.aligned.m8n8.x4.shared.b16 {%0,%1,%2,%3}, [%4];"
                 : "=r"(r[0]), "=r"(r[1]), "=r"(r[2]), "=r"(r[3]) : "r"(addr));
}

__device__ __forceinline__ void ldm_x4t(uint32_t* r, uint32_t addr) {
    asm volatile("ldmatrix.sync.aligned.m8n8.x4.trans.shared.b16 {%0,%1,%2,%3}, [%4];"
                 : "=r"(r[0]), "=r"(r[1]), "=r"(r[2]), "=r"(r[3]) : "r"(addr));
}

__device__ __forceinline__ void mma16816(float* c, const uint32_t* a,
                                         uint32_t b0, uint32_t b1) {
    asm volatile("mma.sync.aligned.m16n8k16.row.col.f32.bf16.bf16.f32 "
                 "{%0,%1,%2,%3}, {%4,%5,%6,%7}, {%8,%9}, {%0,%1,%2,%3};"
                 : "+f"(c[0]), "+f"(c[1]), "+f"(c[2]), "+f"(c[3])
                 : "r"(a[0]), "r"(a[1]), "r"(a[2]), "r"(a[3]), "r"(b0), "r"(b1));
}

__device__ __forceinline__ uint32_t pack_hi(float x, float y, float& rx, float& ry) {
    __nv_bfloat16 hx = __float2bfloat16_rn(x);
    __nv_bfloat16 hy = __float2bfloat16_rn(y);
    rx = x - __bfloat162float(hx);
    ry = y - __bfloat162float(hy);
    __nv_bfloat162 h(hx, hy);
    return *reinterpret_cast<uint32_t*>(&h);
}

__device__ __forceinline__ uint32_t pack_lo(float rx, float ry) {
    __nv_bfloat162 l = __floats2bfloat162_rn(rx, ry);
    return *reinterpret_cast<uint32_t*>(&l);
}

// ---------------- degree / norm / CSR build ----------------

__global__ void deg_count(const int* __restrict__ dst, int* deg, int e) {
    int i = blockIdx.x * blockDim.x + threadIdx.x;
    if (i < e) atomicAdd(&deg[dst[i]], 1);
}

__global__ void dinv_fin(const int* __restrict__ deg, float* dinv, int n) {
    int i = blockIdx.x * blockDim.x + threadIdx.x;
    if (i < n) dinv[i] = rsqrtf((float)(deg[i] + 1));
}

__global__ __launch_bounds__(512) void scan1(const int* __restrict__ deg, int* blockSums, int n) {
    __shared__ int sm[512];
    int t = threadIdx.x;
    int i = blockIdx.x * 512 + t;
    sm[t] = (i < n) ? deg[i] : 0;
    __syncthreads();
    for (int o = 256; o > 0; o >>= 1) {
        if (t < o) sm[t] += sm[t + o];
        __syncthreads();
    }
    if (t == 0) blockSums[blockIdx.x] = sm[0];
}

__global__ __launch_bounds__(512) void scan3f(const int* __restrict__ deg,
                                              const int* __restrict__ blockSums,
                                              int* rowptr, int* cursor, int n, int nb) {
    __shared__ int sb[256];
    __shared__ int sm[512];
    int t = threadIdx.x;
    if (t < 256) sb[t] = (t < nb) ? blockSums[t] : 0;
    __syncthreads();
    for (int o = 1; o < 256; o <<= 1) {
        int x = (t < 256 && t >= o) ? sb[t - o] : 0;
        __syncthreads();
        if (t < 256) sb[t] += x;
        __syncthreads();
    }
    int blockOffset = (blockIdx.x > 0) ? sb[blockIdx.x - 1] : 0;

    int i = blockIdx.x * 512 + t;
    int v = (i < n) ? deg[i] : 0;
    sm[t] = v;
    __syncthreads();
    for (int o = 1; o < 512; o <<= 1) {
        int x = (t >= o) ? sm[t - o] : 0;
        __syncthreads();
        sm[t] += x;
        __syncthreads();
    }
    if (i < n) {
        int r = blockOffset + sm[t] - v;
        rowptr[i] = r;
        cursor[i] = r;
    }
}

__global__ void fill_adj(const int* __restrict__ src, const int* __restrict__ dst,
                         int* cursor, int* adj, int e) {
    int i = blockIdx.x * blockDim.x + threadIdx.x;
    if (i < e) {
        int pos = atomicAdd(&cursor[dst[i]], 1);
        adj[pos] = src[i];
    }
}

// ---------------- split-bf16 HMMA GEMM v2 (node-range capable) ----------------

template<int NC, bool RELU>
__global__ __launch_bounds__(256, 2) void gemm_hmma(const float* __restrict__ A,
                                                    const float* __restrict__ W,
                                                    const float* __restrict__ dinv,
                                                    float* __restrict__ G, int n, int mBase) {
    constexpr int SKA = 40;
    constexpr int SNB = NC + 8;
    constexpr int NTW = NC / 16;
    constexpr int NP  = NTW / 2;

    __shared__ __nv_bfloat16 sAh[128 * SKA];
    __shared__ __nv_bfloat16 sAl[128 * SKA];
    __shared__ __nv_bfloat16 sBh[32 * SNB];
    __shared__ __nv_bfloat16 sBl[32 * SNB];

    int tid = threadIdx.x;
    int wid = tid >> 5;
    int lane = tid & 31;
    int wm = wid & 3;
    int wn = wid >> 2;
    int row0 = mBase + blockIdx.x * 128;

    uint32_t bAh = smem_u32(sAh), bAl = smem_u32(sAl);
    uint32_t bBh = smem_u32(sBh), bBl = smem_u32(sBl);

    float acc[2][NTW][4];
#pragma unroll
    for (int mt = 0; mt < 2; mt++)
#pragma unroll
        for (int t = 0; t < NTW; t++)
#pragma unroll
            for (int j = 0; j < 4; j++) acc[mt][t][j] = 0.f;

#pragma unroll 1
    for (int ch = 0; ch < 4; ch++) {
        int k0c = ch * 32;

#pragma unroll
        for (int j = 0; j < 4; j++) {
            int s = tid + j * 256;
            int row = s >> 3;
            int kg = s & 7;
            int gr = row0 + row;
            float4 v = make_float4(0.f, 0.f, 0.f, 0.f);
            if (gr < n) v = *reinterpret_cast<const float4*>(&A[(long)gr * 128 + k0c + kg * 4]);
            if (RELU) {
                v.x = fmaxf(v.x, 0.f); v.y = fmaxf(v.y, 0.f);
                v.z = fmaxf(v.z, 0.f); v.w = fmaxf(v.w, 0.f);
            }
            float rx, ry, rz, rw;
            uint2 h, l;
            h.x = pack_hi(v.x, v.y, rx, ry);
            h.y = pack_hi(v.z, v.w, rz, rw);
            l.x = pack_lo(rx, ry);
            l.y = pack_lo(rz, rw);
            *reinterpret_cast<uint2*>(&sAh[row * SKA + kg * 4]) = h;
            *reinterpret_cast<uint2*>(&sAl[row * SKA + kg * 4]) = l;
        }

#pragma unroll
        for (int j = 0; j < NC / 32; j++) {
            int s = tid + j * 256;
            int krow = s / (NC / 4);
            int ng = s % (NC / 4);
            float4 v = *reinterpret_cast<const float4*>(&W[(long)(k0c + krow) * NC + ng * 4]);
            float rx, ry, rz, rw;
            uint2 h, l;
            h.x = pack_hi(v.x, v.y, rx, ry);
            h.y = pack_hi(v.z, v.w, rz, rw);
            l.x = pack_lo(rx, ry);
            l.y = pack_lo(rz, rw);
            *reinterpret_cast<uint2*>(&sBh[krow * SNB + ng * 4]) = h;
            *reinterpret_cast<uint2*>(&sBl[krow * SNB + ng * 4]) = l;
        }
        __syncthreads();

#pragma unroll
        for (int ks = 0; ks < 2; ks++) {
            uint32_t aH[2][4], aL[2][4];
            int lrow = lane & 15;
            int lk = ks * 16 + ((lane >> 4) & 1) * 8;
#pragma unroll
            for (int mt = 0; mt < 2; mt++) {
                uint32_t off = (uint32_t)((wm * 32 + mt * 16 + lrow) * SKA + lk) * 2;
                ldm_x4(aH[mt], bAh + off);
                ldm_x4(aL[mt], bAl + off);
            }

#pragma unroll
            for (int np = 0; np < NP; np++) {
                int n0 = wn * (NC / 2) + np * 16;
                int kr = ks * 16 + (lane & 15);
                int ncol = n0 + ((lane >> 4) & 1) * 8;
                uint32_t boff = (uint32_t)(kr * SNB + ncol) * 2;
                uint32_t bH[4], bL[4];
                ldm_x4t(bH, bBh + boff);
                ldm_x4t(bL, bBl + boff);
#pragma unroll
                for (int h = 0; h < 2; h++) {
                    int t = np * 2 + h;
#pragma unroll
                    for (int mt = 0; mt < 2; mt++) {
                        mma16816(acc[mt][t], aH[mt], bH[2 * h], bH[2 * h + 1]);
                        mma16816(acc[mt][t], aL[mt], bH[2 * h], bH[2 * h + 1]);
                        mma16816(acc[mt][t], aH[mt], bL[2 * h], bL[2 * h + 1]);
                    }
                }
            }
        }
        __syncthreads();
    }

#pragma unroll
    for (int mt = 0; mt < 2; mt++) {
        int r0 = row0 + wm * 32 + mt * 16 + (lane >> 2);
        int r1 = r0 + 8;
        float sc0 = (r0 < n) ? __ldg(&dinv[r0]) : 0.f;
        float sc1 = (r1 < n) ? __ldg(&dinv[r1]) : 0.f;
#pragma unroll
        for (int t = 0; t < NTW; t++) {
            int col = wn * (NC / 2) + t * 8 + (lane & 3) * 2;
            if (r0 < n) {
                float2 o = make_float2(acc[mt][t][0] * sc0, acc[mt][t][1] * sc0);
                *reinterpret_cast<float2*>(&G[(long)r0 * NC + col]) = o;
            }
            if (r1 < n) {
                float2 o = make_float2(acc[mt][t][2] * sc1, acc[mt][t][3] * sc1);
                *reinterpret_cast<float2*>(&G[(long)r1 * NC + col]) = o;
            }
        }
    }
}

// ---------------- gather aggregate (x4 unroll; node-range capable) ----------------

template<int F>
__global__ __launch_bounds__(256) void gather_k(const float* __restrict__ G,
                                                const int* __restrict__ adj,
                                                const int* __restrict__ rowptr,
                                                const int* __restrict__ deg,
                                                const float* __restrict__ dinv,
                                                const float* __restrict__ b,
                                                float* __restrict__ OUT,
                                                int nodeBase, int nodeEnd) {
    int gw = nodeBase + ((blockIdx.x * blockDim.x + threadIdx.x) >> 5);
    int lane = threadIdx.x & 31;
    if (gw >= nodeEnd) return;

    int start = rowptr[gw];
    int cnt = deg[gw];

    if (F == 128) {
        float4 acc = reinterpret_cast<const float4*>(G + (long)gw * F)[lane];
        for (int c = 0; c < cnt; c += 32) {
            int my = 0;
            if (c + lane < cnt) my = __ldg(&adj[start + c + lane]);
            int mend = min(32, cnt - c);
            int m = 0;
            for (; m + 4 <= mend; m += 4) {
                int s0 = __shfl_sync(0xffffffffu, my, m + 0);
                int s1 = __shfl_sync(0xffffffffu, my, m + 1);
                int s2 = __shfl_sync(0xffffffffu, my, m + 2);
                int s3 = __shfl_sync(0xffffffffu, my, m + 3);
                float4 v0 = reinterpret_cast<const float4*>(G + (long)s0 * F)[lane];
                float4 v1 = reinterpret_cast<const float4*>(G + (long)s1 * F)[lane];
                float4 v2 = reinterpret_cast<const float4*>(G + (long)s2 * F)[lane];
                float4 v3 = reinterpret_cast<const float4*>(G + (long)s3 * F)[lane];
                acc.x += v0.x + v1.x + v2.x + v3.x;
                acc.y += v0.y + v1.y + v2.y + v3.y;
                acc.z += v0.z + v1.z + v2.z + v3.z;
                acc.w += v0.w + v1.w + v2.w + v3.w;
            }
            for (; m < mend; m++) {
                int s = __shfl_sync(0xffffffffu, my, m);
                float4 v = reinterpret_cast<const float4*>(G + (long)s * F)[lane];
                acc.x += v.x; acc.y += v.y; acc.z += v.z; acc.w += v.w;
            }
        }
        float sc = dinv[gw];
        float4 bb = reinterpret_cast<const float4*>(b)[lane];
        float4 r;
        r.x = fmaf(acc.x, sc, bb.x);
        r.y = fmaf(acc.y, sc, bb.y);
        r.z = fmaf(acc.z, sc, bb.z);
        r.w = fmaf(acc.w, sc, bb.w);
        reinterpret_cast<float4*>(OUT + (long)gw * F)[lane] = r;
    } else {
        float2 acc = reinterpret_cast<const float2*>(G + (long)gw * F)[lane];
        for (int c = 0; c < cnt; c += 32) {
            int my = 0;
            if (c + lane < cnt) my = __ldg(&adj[start + c + lane]);
            int mend = min(32, cnt - c);
            int m = 0;
            for (; m + 4 <= mend; m += 4) {
                int s0 = __shfl_sync(0xffffffffu, my, m + 0);
                int s1 = __shfl_sync(0xffffffffu, my, m + 1);
                int s2 = __shfl_sync(0xffffffffu, my, m + 2);
                int s3 = __shfl_sync(0xffffffffu, my, m + 3);
                float2 v0 = reinterpret_cast<const float2*>(G + (long)s0 * F)[lane];
                float2 v1 = reinterpret_cast<const float2*>(G + (long)s1 * F)[lane];
                float2 v2 = reinterpret_cast<const float2*>(G + (long)s2 * F)[lane];
                float2 v3 = reinterpret_cast<const float2*>(G + (long)s3 * F)[lane];
                acc.x += v0.x + v1.x + v2.x + v3.x;
                acc.y += v0.y + v1.y + v2.y + v3.y;
            }
            for (; m < mend; m++) {
                int s = __shfl_sync(0xffffffffu, my, m);
                float2 v = reinterpret_cast<const float2*>(G + (long)s * F)[lane];
                acc.x += v.x; acc.y += v.y;
            }
        }
        float sc = dinv[gw];
        float2 bb = reinterpret_cast<const float2*>(b)[lane];
        float2 r;
        r.x = fmaf(acc.x, sc, bb.x);
        r.y = fmaf(acc.y, sc, bb.y);
        reinterpret_cast<float2*>(OUT + (long)gw * F)[lane] = r;
    }
}

// ---------------- launch ----------------

extern "C" void kernel_launch(void* const* d_in, const int* in_sizes, int n_in,
                              void* d_out, int out_size) {
    const float* x  = (const float*)d_in[0];
    const int*   ei = (const int*)  d_in[1];
    const float* W1 = (const float*)d_in[2];
    const float* b1 = (const float*)d_in[3];
    const float* W2 = (const float*)d_in[4];
    const float* b2 = (const float*)d_in[5];
    const float* W3 = (const float*)d_in[6];
    const float* b3 = (const float*)d_in[7];
    float* out = (float*)d_out;

    int n = in_sizes[0] / FIN;
    int e = in_sizes[1] / 2;
    const int* srcp = ei;
    const int* dstp = ei + e;

    float *dinv, *GA, *GB, *ACC;
    int *deg, *rowptr, *cursor, *adj, *blockSums;
    cudaGetSymbolAddress((void**)&dinv, g_dinv);
    cudaGetSymbolAddress((void**)&deg,  g_deg);
    cudaGetSymbolAddress((void**)&rowptr, g_rowptr);
    cudaGetSymbolAddress((void**)&cursor, g_cursor);
    cudaGetSymbolAddress((void**)&adj,  g_adj);
    cudaGetSymbolAddress((void**)&blockSums, g_blockSums);
    cudaGetSymbolAddress((void**)&GA,   g_GA);
    cudaGetSymbolAddress((void**)&GB,   g_GB);
    cudaGetSymbolAddress((void**)&ACC,  g_ACC);

    const int T = 256;
    int gN = (n + T - 1) / T;
    int gE = (e + T - 1) / T;
    int nb = (n + 511) / 512;

    int nh = ((n / 2) + 127) & ~127;     // half boundary, multiple of 128
    int gM0 = nh / 128;
    int gM1 = (n - nh + 127) / 128;
    int gM  = (n + 127) / 128;
    int gW0 = (nh * 32 + T - 1) / T;
    int gW1 = ((n - nh) * 32 + T - 1) / T;
    int gW  = (n * 32 + T - 1) / T;

    static cudaStream_t s1 = []{ cudaStream_t s; cudaStreamCreateWithFlags(&s, cudaStreamNonBlocking); return s; }();
    static cudaEvent_t e0 = []{ cudaEvent_t v; cudaEventCreateWithFlags(&v, cudaEventDisableTiming); return v; }();
    static cudaEvent_t e1 = []{ cudaEvent_t v; cudaEventCreateWithFlags(&v, cudaEventDisableTiming); return v; }();
    static cudaEvent_t e2 = []{ cudaEvent_t v; cudaEventCreateWithFlags(&v, cudaEventDisableTiming); return v; }();
    static cudaEvent_t e3 = []{ cudaEvent_t v; cudaEventCreateWithFlags(&v, cudaEventDisableTiming); return v; }();
    static cudaEvent_t e4 = []{ cudaEvent_t v; cudaEventCreateWithFlags(&v, cudaEventDisableTiming); return v; }();
    static cudaEvent_t e5 = []{ cudaEvent_t v; cudaEventCreateWithFlags(&v, cudaEventDisableTiming); return v; }();

    // ---- serial prefix: degree + dinv ----
    cudaMemsetAsync(deg, 0, n * sizeof(int), 0);
    deg_count<<<gE, T>>>(dstp, deg, e);
    dinv_fin<<<gN, T>>>(deg, dinv, n);

    // ---- fork: CSR scan/fill on s1 || gemm1 (full) -> GA on main ----
    cudaEventRecord(e0, 0);
    cudaStreamWaitEvent(s1, e0, 0);
    scan1<<<nb, 512, 0, s1>>>(deg, blockSums, n);
    scan3f<<<nb, 512, 0, s1>>>(deg, blockSums, rowptr, cursor, n, nb);
    fill_adj<<<gE, T, 0, s1>>>(srcp, dstp, cursor, adj, e);
    cudaEventRecord(e1, s1);

    gemm_hmma<FHID, false><<<gM, T>>>(x, W1, dinv, GA, n, 0);

    cudaStreamWaitEvent(0, e1, 0);

    // ---- layer 1 gather h0 (main): GA -> ACC[0:nh] ----
    gather_k<FHID><<<gW0, T>>>(GA, adj, rowptr, deg, dinv, b1, ACC, 0, nh);

    // fork: gather1_h1 (s1, reads GA) || gemm2_h0 (main, reads ACC[0:nh], writes GB[0:nh])
    cudaEventRecord(e2, 0);
    cudaStreamWaitEvent(s1, e2, 0);
    gather_k<FHID><<<gW1, T, 0, s1>>>(GA, adj, rowptr, deg, dinv, b1, ACC, nh, n);
    cudaEventRecord(e3, s1);

    gemm_hmma<FHID, true><<<gM0, T>>>(ACC, W2, dinv, GB, n, 0);

    cudaStreamWaitEvent(0, e3, 0);
    gemm_hmma<FHID, true><<<gM1, T>>>(ACC, W2, dinv, GB, n, nh);

    // ---- layer 2 gather h0 (main): GB -> ACC[0:nh] ----
    gather_k<FHID><<<gW0, T>>>(GB, adj, rowptr, deg, dinv, b2, ACC, 0, nh);

    // fork: gather2_h1 (s1, reads GB) || gemm3_h0 (main, writes GA[0:nh])
    cudaEventRecord(e4, 0);
    cudaStreamWaitEvent(s1, e4, 0);
    gather_k<FHID><<<gW1, T, 0, s1>>>(GB, adj, rowptr, deg, dinv, b2, ACC, nh, n);
    cudaEventRecord(e5, s1);

    gemm_hmma<FOUT, true><<<gM0, T>>>(ACC, W3, dinv, GA, n, 0);

    cudaStreamWaitEvent(0, e5, 0);
    gemm_hmma<FOUT, true><<<gM1, T>>>(ACC, W3, dinv, GA, n, nh);

    // ---- layer 3 gather (full, main): GA -> out ----
    gather_k<FOUT><<<gW, T>>>(GA, adj, rowptr, deg, dinv, b3, out, 0, n);
}

// round 15
// speedup vs baseline: 1.2401x; 1.2401x over previous
#include <cuda_runtime.h>
#include <cuda_bf16.h>
#include <cuda_fp16.h>
#include <cstdint>

#define NNODES 100000
#define NEDGES 1600000
#define FIN  128
#define FHID 128
#define FOUT 64

// Scratch (allocation-free rule: __device__ globals)
__device__ float  g_dinv[NNODES];
__device__ int    g_deg [NNODES];
__device__ int    g_rowptr[NNODES];
__device__ int    g_cursor[NNODES];
__device__ int    g_adj [NEDGES];
__device__ int    g_blockSums[256];
__device__ __half g_G  [NNODES * FHID];   // fp16 message buffer (dinv[v]*h_v)
__device__ float  g_ACC[NNODES * FHID];   // aggregated output / next-layer input (fp32)

// ---------------- helpers ----------------

__device__ __forceinline__ uint32_t smem_u32(const void* p) {
    uint32_t a;
    asm("{ .reg .u64 t; cvta.to.shared.u64 t, %1; cvt.u32.u64 %0, t; }" : "=r"(a) : "l"(p));
    return a;
}

__device__ __forceinline__ void ldm_x4(uint32_t* r, uint32_t addr) {
    asm volatile("ldmatrix.sync.aligned.m8n8.x4.shared.b16 {%0,%1,%2,%3}, [%4];"
                 : "=r"(r[0]), "=r"(r[1]), "=r"(r[2]), "=r"(r[3]) : "r"(addr));
}

__device__ __forceinline__ void ldm_x4t(uint32_t* r, uint32_t addr) {
    asm volatile("ldmatrix.sync.aligned.m8n8.x4.trans.shared.b16 {%0,%1,%2,%3}, [%4];"
                 : "=r"(r[0]), "=r"(r[1]), "=r"(r[2]), "=r"(r[3]) : "r"(addr));
}

__device__ __forceinline__ void mma16816(float* c, const uint32_t* a,
                                         uint32_t b0, uint32_t b1) {
    asm volatile("mma.sync.aligned.m16n8k16.row.col.f32.bf16.bf16.f32 "
                 "{%0,%1,%2,%3}, {%4,%5,%6,%7}, {%8,%9}, {%0,%1,%2,%3};"
                 : "+f"(c[0]), "+f"(c[1]), "+f"(c[2]), "+f"(c[3])
                 : "r"(a[0]), "r"(a[1]), "r"(a[2]), "r"(a[3]), "r"(b0), "r"(b1));
}

__device__ __forceinline__ uint32_t pack_hi(float x, float y, float& rx, float& ry) {
    __nv_bfloat16 hx = __float2bfloat16_rn(x);
    __nv_bfloat16 hy = __float2bfloat16_rn(y);
    rx = x - __bfloat162float(hx);
    ry = y - __bfloat162float(hy);
    __nv_bfloat162 h(hx, hy);
    return *reinterpret_cast<uint32_t*>(&h);
}

__device__ __forceinline__ uint32_t pack_lo(float rx, float ry) {
    __nv_bfloat162 l = __floats2bfloat162_rn(rx, ry);
    return *reinterpret_cast<uint32_t*>(&l);
}

// ---------------- degree / norm / CSR build ----------------

__global__ void deg_count(const int* __restrict__ dst, int* deg, int e) {
    int i = blockIdx.x * blockDim.x + threadIdx.x;
    if (i < e) atomicAdd(&deg[dst[i]], 1);
}

__global__ void dinv_fin(const int* __restrict__ deg, float* dinv, int n) {
    int i = blockIdx.x * blockDim.x + threadIdx.x;
    if (i < n) dinv[i] = rsqrtf((float)(deg[i] + 1));
}

__global__ __launch_bounds__(512) void scan1(const int* __restrict__ deg, int* blockSums, int n) {
    __shared__ int sm[512];
    int t = threadIdx.x;
    int i = blockIdx.x * 512 + t;
    sm[t] = (i < n) ? deg[i] : 0;
    __syncthreads();
    for (int o = 256; o > 0; o >>= 1) {
        if (t < o) sm[t] += sm[t + o];
        __syncthreads();
    }
    if (t == 0) blockSums[blockIdx.x] = sm[0];
}

__global__ __launch_bounds__(512) void scan3f(const int* __restrict__ deg,
                                              const int* __restrict__ blockSums,
                                              int* rowptr, int* cursor, int n, int nb) {
    __shared__ int sb[256];
    __shared__ int sm[512];
    int t = threadIdx.x;
    if (t < 256) sb[t] = (t < nb) ? blockSums[t] : 0;
    __syncthreads();
    for (int o = 1; o < 256; o <<= 1) {
        int x = (t < 256 && t >= o) ? sb[t - o] : 0;
        __syncthreads();
        if (t < 256) sb[t] += x;
        __syncthreads();
    }
    int blockOffset = (blockIdx.x > 0) ? sb[blockIdx.x - 1] : 0;

    int i = blockIdx.x * 512 + t;
    int v = (i < n) ? deg[i] : 0;
    sm[t] = v;
    __syncthreads();
    for (int o = 1; o < 512; o <<= 1) {
        int x = (t >= o) ? sm[t - o] : 0;
        __syncthreads();
        sm[t] += x;
        __syncthreads();
    }
    if (i < n) {
        int r = blockOffset + sm[t] - v;
        rowptr[i] = r;
        cursor[i] = r;
    }
}

__global__ void fill_adj(const int* __restrict__ src, const int* __restrict__ dst,
                         int* cursor, int* adj, int e) {
    int i = blockIdx.x * blockDim.x + threadIdx.x;
    if (i < e) {
        int pos = atomicAdd(&cursor[dst[i]], 1);
        adj[pos] = src[i];
    }
}

// ---------------- split-bf16 HMMA GEMM v2 (fp16 output) ----------------

template<int NC, bool RELU>
__global__ __launch_bounds__(256, 2) void gemm_hmma(const float* __restrict__ A,
                                                    const float* __restrict__ W,
                                                    const float* __restrict__ dinv,
                                                    __half* __restrict__ G, int n) {
    constexpr int SKA = 40;
    constexpr int SNB = NC + 8;
    constexpr int NTW = NC / 16;
    constexpr int NP  = NTW / 2;

    __shared__ __nv_bfloat16 sAh[128 * SKA];
    __shared__ __nv_bfloat16 sAl[128 * SKA];
    __shared__ __nv_bfloat16 sBh[32 * SNB];
    __shared__ __nv_bfloat16 sBl[32 * SNB];

    int tid = threadIdx.x;
    int wid = tid >> 5;
    int lane = tid & 31;
    int wm = wid & 3;
    int wn = wid >> 2;
    int row0 = blockIdx.x * 128;

    uint32_t bAh = smem_u32(sAh), bAl = smem_u32(sAl);
    uint32_t bBh = smem_u32(sBh), bBl = smem_u32(sBl);

    float acc[2][NTW][4];
#pragma unroll
    for (int mt = 0; mt < 2; mt++)
#pragma unroll
        for (int t = 0; t < NTW; t++)
#pragma unroll
            for (int j = 0; j < 4; j++) acc[mt][t][j] = 0.f;

#pragma unroll 1
    for (int ch = 0; ch < 4; ch++) {
        int k0c = ch * 32;

#pragma unroll
        for (int j = 0; j < 4; j++) {
            int s = tid + j * 256;
            int row = s >> 3;
            int kg = s & 7;
            int gr = row0 + row;
            float4 v = make_float4(0.f, 0.f, 0.f, 0.f);
            if (gr < n) v = *reinterpret_cast<const float4*>(&A[(long)gr * 128 + k0c + kg * 4]);
            if (RELU) {
                v.x = fmaxf(v.x, 0.f); v.y = fmaxf(v.y, 0.f);
                v.z = fmaxf(v.z, 0.f); v.w = fmaxf(v.w, 0.f);
            }
            float rx, ry, rz, rw;
            uint2 h, l;
            h.x = pack_hi(v.x, v.y, rx, ry);
            h.y = pack_hi(v.z, v.w, rz, rw);
            l.x = pack_lo(rx, ry);
            l.y = pack_lo(rz, rw);
            *reinterpret_cast<uint2*>(&sAh[row * SKA + kg * 4]) = h;
            *reinterpret_cast<uint2*>(&sAl[row * SKA + kg * 4]) = l;
        }

#pragma unroll
        for (int j = 0; j < NC / 32; j++) {
            int s = tid + j * 256;
            int krow = s / (NC / 4);
            int ng = s % (NC / 4);
            float4 v = *reinterpret_cast<const float4*>(&W[(long)(k0c + krow) * NC + ng * 4]);
            float rx, ry, rz, rw;
            uint2 h, l;
            h.x = pack_hi(v.x, v.y, rx, ry);
            h.y = pack_hi(v.z, v.w, rz, rw);
            l.x = pack_lo(rx, ry);
            l.y = pack_lo(rz, rw);
            *reinterpret_cast<uint2*>(&sBh[krow * SNB + ng * 4]) = h;
            *reinterpret_cast<uint2*>(&sBl[krow * SNB + ng * 4]) = l;
        }
        __syncthreads();

#pragma unroll
        for (int ks = 0; ks < 2; ks++) {
            uint32_t aH[2][4], aL[2][4];
            int lrow = lane & 15;
            int lk = ks * 16 + ((lane >> 4) & 1) * 8;
#pragma unroll
            for (int mt = 0; mt < 2; mt++) {
                uint32_t off = (uint32_t)((wm * 32 + mt * 16 + lrow) * SKA + lk) * 2;
                ldm_x4(aH[mt], bAh + off);
                ldm_x4(aL[mt], bAl + off);
            }

#pragma unroll
            for (int np = 0; np < NP; np++) {
                int n0 = wn * (NC / 2) + np * 16;
                int kr = ks * 16 + (lane & 15);
                int ncol = n0 + ((lane >> 4) & 1) * 8;
                uint32_t boff = (uint32_t)(kr * SNB + ncol) * 2;
                uint32_t bH[4], bL[4];
                ldm_x4t(bH, bBh + boff);
                ldm_x4t(bL, bBl + boff);
#pragma unroll
                for (int h = 0; h < 2; h++) {
                    int t = np * 2 + h;
#pragma unroll
                    for (int mt = 0; mt < 2; mt++) {
                        mma16816(acc[mt][t], aH[mt], bH[2 * h], bH[2 * h + 1]);
                        mma16816(acc[mt][t], aL[mt], bH[2 * h], bH[2 * h + 1]);
                        mma16816(acc[mt][t], aH[mt], bL[2 * h], bL[2 * h + 1]);
                    }
                }
            }
        }
        __syncthreads();
    }

    // ---- epilogue: fp16 store, scaled by dinv ----
#pragma unroll
    for (int mt = 0; mt < 2; mt++) {
        int r0 = row0 + wm * 32 + mt * 16 + (lane >> 2);
        int r1 = r0 + 8;
        float sc0 = (r0 < n) ? __ldg(&dinv[r0]) : 0.f;
        float sc1 = (r1 < n) ? __ldg(&dinv[r1]) : 0.f;
#pragma unroll
        for (int t = 0; t < NTW; t++) {
            int col = wn * (NC / 2) + t * 8 + (lane & 3) * 2;
            if (r0 < n) {
                __half2 o = __floats2half2_rn(acc[mt][t][0] * sc0, acc[mt][t][1] * sc0);
                *reinterpret_cast<__half2*>(&G[(long)r0 * NC + col]) = o;
            }
            if (r1 < n) {
                __half2 o = __floats2half2_rn(acc[mt][t][2] * sc1, acc[mt][t][3] * sc1);
                *reinterpret_cast<__half2*>(&G[(long)r1 * NC + col]) = o;
            }
        }
    }
}

// ---------------- gather aggregate (x4 unroll, fp16 messages, fp32 accumulate) ----------------

template<int F>
__global__ __launch_bounds__(256) void gather_k(const __half* __restrict__ G,
                                                const int* __restrict__ adj,
                                                const int* __restrict__ rowptr,
                                                const int* __restrict__ deg,
                                                const float* __restrict__ dinv,
                                                const float* __restrict__ b,
                                                float* __restrict__ OUT, int n) {
    int gw = (blockIdx.x * blockDim.x + threadIdx.x) >> 5;
    int lane = threadIdx.x & 31;
    if (gw >= n) return;

    int start = rowptr[gw];
    int cnt = deg[gw];

    if (F == 128) {
        // lane covers 4 halves (8 B)
        uint2 us = reinterpret_cast<const uint2*>(G + (long)gw * F)[lane];
        float2 p0 = __half22float2(*reinterpret_cast<__half2*>(&us.x));
        float2 p1 = __half22float2(*reinterpret_cast<__half2*>(&us.y));
        float4 acc = make_float4(p0.x, p0.y, p1.x, p1.y);
        for (int c = 0; c < cnt; c += 32) {
            int my = 0;
            if (c + lane < cnt) my = __ldg(&adj[start + c + lane]);
            int mend = min(32, cnt - c);
            int m = 0;
            for (; m + 4 <= mend; m += 4) {
                int s0 = __shfl_sync(0xffffffffu, my, m + 0);
                int s1 = __shfl_sync(0xffffffffu, my, m + 1);
                int s2 = __shfl_sync(0xffffffffu, my, m + 2);
                int s3 = __shfl_sync(0xffffffffu, my, m + 3);
                uint2 u0 = reinterpret_cast<const uint2*>(G + (long)s0 * F)[lane];
                uint2 u1 = reinterpret_cast<const uint2*>(G + (long)s1 * F)[lane];
                uint2 u2 = reinterpret_cast<const uint2*>(G + (long)s2 * F)[lane];
                uint2 u3 = reinterpret_cast<const uint2*>(G + (long)s3 * F)[lane];
                float2 a0 = __half22float2(*reinterpret_cast<__half2*>(&u0.x));
                float2 a1 = __half22float2(*reinterpret_cast<__half2*>(&u0.y));
                float2 b0 = __half22float2(*reinterpret_cast<__half2*>(&u1.x));
                float2 b1 = __half22float2(*reinterpret_cast<__half2*>(&u1.y));
                float2 c0 = __half22float2(*reinterpret_cast<__half2*>(&u2.x));
                float2 c1 = __half22float2(*reinterpret_cast<__half2*>(&u2.y));
                float2 d0 = __half22float2(*reinterpret_cast<__half2*>(&u3.x));
                float2 d1 = __half22float2(*reinterpret_cast<__half2*>(&u3.y));
                acc.x += (a0.x + b0.x) + (c0.x + d0.x);
                acc.y += (a0.y + b0.y) + (c0.y + d0.y);
                acc.z += (a1.x + b1.x) + (c1.x + d1.x);
                acc.w += (a1.y + b1.y) + (c1.y + d1.y);
            }
            for (; m < mend; m++) {
                int s = __shfl_sync(0xffffffffu, my, m);
                uint2 u = reinterpret_cast<const uint2*>(G + (long)s * F)[lane];
                float2 a0 = __half22float2(*reinterpret_cast<__half2*>(&u.x));
                float2 a1 = __half22float2(*reinterpret_cast<__half2*>(&u.y));
                acc.x += a0.x; acc.y += a0.y; acc.z += a1.x; acc.w += a1.y;
            }
        }
        float sc = dinv[gw];
        float4 bb = reinterpret_cast<const float4*>(b)[lane];
        float4 r;
        r.x = fmaf(acc.x, sc, bb.x);
        r.y = fmaf(acc.y, sc, bb.y);
        r.z = fmaf(acc.z, sc, bb.z);
        r.w = fmaf(acc.w, sc, bb.w);
        reinterpret_cast<float4*>(OUT + (long)gw * F)[lane] = r;
    } else {
        // F=64: lane covers 2 halves (4 B)
        uint32_t us = reinterpret_cast<const uint32_t*>(G + (long)gw * F)[lane];
        float2 acc = __half22float2(*reinterpret_cast<__half2*>(&us));
        for (int c = 0; c < cnt; c += 32) {
            int my = 0;
            if (c + lane < cnt) my = __ldg(&adj[start + c + lane]);
            int mend = min(32, cnt - c);
            int m = 0;
            for (; m + 4 <= mend; m += 4) {
                int s0 = __shfl_sync(0xffffffffu, my, m + 0);
                int s1 = __shfl_sync(0xffffffffu, my, m + 1);
                int s2 = __shfl_sync(0xffffffffu, my, m + 2);
                int s3 = __shfl_sync(0xffffffffu, my, m + 3);
                uint32_t u0 = reinterpret_cast<const uint32_t*>(G + (long)s0 * F)[lane];
                uint32_t u1 = reinterpret_cast<const uint32_t*>(G + (long)s1 * F)[lane];
                uint32_t u2 = reinterpret_cast<const uint32_t*>(G + (long)s2 * F)[lane];
                uint32_t u3 = reinterpret_cast<const uint32_t*>(G + (long)s3 * F)[lane];
                float2 a0 = __half22float2(*reinterpret_cast<__half2*>(&u0));
                float2 a1 = __half22float2(*reinterpret_cast<__half2*>(&u1));
                float2 a2 = __half22float2(*reinterpret_cast<__half2*>(&u2));
                float2 a3 = __half22float2(*reinterpret_cast<__half2*>(&u3));
                acc.x += (a0.x + a1.x) + (a2.x + a3.x);
                acc.y += (a0.y + a1.y) + (a2.y + a3.y);
            }
            for (; m < mend; m++) {
                int s = __shfl_sync(0xffffffffu, my, m);
                uint32_t u = reinterpret_cast<const uint32_t*>(G + (long)s * F)[lane];
                float2 a = __half22float2(*reinterpret_cast<__half2*>(&u));
                acc.x += a.x; acc.y += a.y;
            }
        }
        float sc = dinv[gw];
        float2 bb = reinterpret_cast<const float2*>(b)[lane];
        float2 r;
        r.x = fmaf(acc.x, sc, bb.x);
        r.y = fmaf(acc.y, sc, bb.y);
        reinterpret_cast<float2*>(OUT + (long)gw * F)[lane] = r;
    }
}

// ---------------- launch ----------------

extern "C" void kernel_launch(void* const* d_in, const int* in_sizes, int n_in,
                              void* d_out, int out_size) {
    const float* x  = (const float*)d_in[0];
    const int*   ei = (const int*)  d_in[1];
    const float* W1 = (const float*)d_in[2];
    const float* b1 = (const float*)d_in[3];
    const float* W2 = (const float*)d_in[4];
    const float* b2 = (const float*)d_in[5];
    const float* W3 = (const float*)d_in[6];
    const float* b3 = (const float*)d_in[7];
    float* out = (float*)d_out;

    int n = in_sizes[0] / FIN;
    int e = in_sizes[1] / 2;
    const int* srcp = ei;
    const int* dstp = ei + e;

    float *dinv, *ACC;
    __half* G;
    int *deg, *rowptr, *cursor, *adj, *blockSums;
    cudaGetSymbolAddress((void**)&dinv, g_dinv);
    cudaGetSymbolAddress((void**)&deg,  g_deg);
    cudaGetSymbolAddress((void**)&rowptr, g_rowptr);
    cudaGetSymbolAddress((void**)&cursor, g_cursor);
    cudaGetSymbolAddress((void**)&adj,  g_adj);
    cudaGetSymbolAddress((void**)&blockSums, g_blockSums);
    cudaGetSymbolAddress((void**)&G,    g_G);
    cudaGetSymbolAddress((void**)&ACC,  g_ACC);

    const int T = 256;
    int gN = (n + T - 1) / T;
    int gE = (e + T - 1) / T;
    int gM = (n + 127) / 128;
    int nb = (n + 511) / 512;
    int gW = (n * 32 + T - 1) / T;

    static cudaStream_t s1 = []{ cudaStream_t s; cudaStreamCreateWithFlags(&s, cudaStreamNonBlocking); return s; }();
    static cudaEvent_t e0 = []{ cudaEvent_t v; cudaEventCreateWithFlags(&v, cudaEventDisableTiming); return v; }();
    static cudaEvent_t e1 = []{ cudaEvent_t v; cudaEventCreateWithFlags(&v, cudaEventDisableTiming); return v; }();

    // ---- serial prefix: degree + dinv ----
    cudaMemsetAsync(deg, 0, n * sizeof(int), 0);
    deg_count<<<gE, T>>>(dstp, deg, e);
    dinv_fin<<<gN, T>>>(deg, dinv, n);

    // ---- fork: CSR scan/fill on s1 || gemm1 on main ----
    cudaEventRecord(e0, 0);
    cudaStreamWaitEvent(s1, e0, 0);
    scan1<<<nb, 512, 0, s1>>>(deg, blockSums, n);
    scan3f<<<nb, 512, 0, s1>>>(deg, blockSums, rowptr, cursor, n, nb);
    fill_adj<<<gE, T, 0, s1>>>(srcp, dstp, cursor, adj, e);
    cudaEventRecord(e1, s1);

    gemm_hmma<FHID, false><<<gM, T>>>(x, W1, dinv, G, n);

    cudaStreamWaitEvent(0, e1, 0);

    // ---- layer 1 ----
    gather_k<FHID><<<gW, T>>>(G, adj, rowptr, deg, dinv, b1, ACC, n);

    // ---- layer 2 ----
    gemm_hmma<FHID, true><<<gM, T>>>(ACC, W2, dinv, G, n);
    gather_k<FHID><<<gW, T>>>(G, adj, rowptr, deg, dinv, b2, ACC, n);

    // ---- layer 3 ----
    gemm_hmma<FOUT, true><<<gM, T>>>(ACC, W3, dinv, G, n);
    gather_k<FOUT><<<gW, T>>>(G, adj, rowptr, deg, dinv, b3, out, n);
}